// round 1
// baseline (speedup 1.0000x reference)
#include <cuda_runtime.h>
#include <math.h>

#define N_Q   6
#define N_CL  32
#define N_MOD 32
#define PART  64
#define B_TOTAL   2048
#define N_CLASSES 150
#define K_FINAL   (N_MOD * N_Q)   // 192
#define FEAT_DIM  2048

#define BT 128  // threads per block in sim kernel

// scratch for per-circuit expectation values: outs[b][p*6+q]
__device__ float g_outs[B_TOTAL * K_FINAL];

__global__ __launch_bounds__(BT, 2) void sim_kernel(
    const float* __restrict__ features,
    const float* __restrict__ Wp,
    const float* __restrict__ bp,
    const float* __restrict__ qw)
{
    __shared__ float s_cs[N_CL][N_Q][2];   // per-layer gate cos/sin (half angle)
    __shared__ float s_Wp[N_Q][PART];
    __shared__ float s_bp[N_Q];

    const int p   = blockIdx.y;                  // module
    const int b   = blockIdx.x * BT + threadIdx.x;
    const int tid = threadIdx.x;

    // cooperative loads: Wp, bp, and this module's layer-gate cos/sin
    for (int i = tid; i < N_Q * PART; i += BT)
        s_Wp[i / PART][i % PART] = Wp[i];
    if (tid < N_Q) s_bp[tid] = bp[tid];
    for (int i = tid; i < N_CL * N_Q; i += BT) {
        float a = qw[p * (N_CL * N_Q) + i];
        float s, c;
        sincosf(0.5f * a, &s, &c);
        s_cs[i / N_Q][i % N_Q][0] = c;
        s_cs[i / N_Q][i % N_Q][1] = s;
    }
    __syncthreads();

    // ---- angle projection: angles[q] = <features[b, p*64 : p*64+64], Wp[q]> + bp[q]
    float acc[N_Q];
#pragma unroll
    for (int q = 0; q < N_Q; q++) acc[q] = s_bp[q];
    const float4* fptr = (const float4*)(features + (size_t)b * FEAT_DIM + p * PART);
#pragma unroll
    for (int d4 = 0; d4 < PART / 4; d4++) {
        float4 f = fptr[d4];
#pragma unroll
        for (int q = 0; q < N_Q; q++) {
            acc[q] += f.x * s_Wp[q][d4 * 4 + 0];
            acc[q] += f.y * s_Wp[q][d4 * 4 + 1];
            acc[q] += f.z * s_Wp[q][d4 * 4 + 2];
            acc[q] += f.w * s_Wp[q][d4 * 4 + 3];
        }
    }
    float ca[N_Q], sa[N_Q];
#pragma unroll
    for (int q = 0; q < N_Q; q++) sincosf(0.5f * acc[q], &sa[q], &ca[q]);

    // ---- initial product state (real): sr[i] = prod_q (bit(i,5-q) ? sa[q] : ca[q])
    float sr[64], si[64];
    sr[0] = 1.0f;
#pragma unroll
    for (int q = 0; q < N_Q; q++) {
        const int len = 1 << q;
#pragma unroll
        for (int i = len - 1; i >= 0; i--) {
            float v = sr[i];
            sr[2 * i]     = v * ca[q];
            sr[2 * i + 1] = v * sa[q];
        }
    }
#pragma unroll
    for (int i = 0; i < 64; i++) si[i] = 0.0f;

    // ---- 32 layers: 6x RX then CNOT ring
    for (int l = 0; l < N_CL; l++) {
#pragma unroll
        for (int q = 0; q < N_Q; q++) {
            const float c = s_cs[l][q][0];
            const float s = s_cs[l][q][1];
            const int bit = 5 - q;       // wire q lives on index bit (5-q)
            const int m   = 1 << bit;
#pragma unroll
            for (int pr = 0; pr < 32; pr++) {
                const int i0 = ((pr >> bit) << (bit + 1)) | (pr & (m - 1));
                const int i1 = i0 | m;
                float r0 = sr[i0], u0 = si[i0];
                float r1 = sr[i1], u1 = si[i1];
                // RX(theta): [[c, -i s], [-i s, c]]
                sr[i0] = c * r0 + s * u1;
                si[i0] = c * u0 - s * r1;
                sr[i1] = c * r1 + s * u0;
                si[i1] = c * u1 - s * r0;
            }
        }
        // CNOT ring: ctrl q -> tgt (q+1)%6, applied in order q = 0..5
#pragma unroll
        for (int q = 0; q < N_Q; q++) {
            const int cb = 5 - q;
            const int tb = 5 - ((q + 1) % N_Q);
            const int tm = 1 << tb;
#pragma unroll
            for (int i = 0; i < 64; i++) {
                if ((((i >> cb) & 1) == 1) && (((i >> tb) & 1) == 0)) {
                    const int j = i | tm;
                    float t;
                    t = sr[i]; sr[i] = sr[j]; sr[j] = t;
                    t = si[i]; si[i] = si[j]; si[j] = t;
                }
            }
        }
    }

    // ---- Z expectations: e[q] = sum_i probs[i] * (1 - 2*bit(i,5-q))
    float e[N_Q];
#pragma unroll
    for (int q = 0; q < N_Q; q++) e[q] = 0.0f;
#pragma unroll
    for (int i = 0; i < 64; i++) {
        float pi = sr[i] * sr[i] + si[i] * si[i];
#pragma unroll
        for (int q = 0; q < N_Q; q++) {
            if ((i >> (5 - q)) & 1) e[q] -= pi; else e[q] += pi;
        }
    }

    float* op = g_outs + (size_t)b * K_FINAL + p * N_Q;
#pragma unroll
    for (int q = 0; q < N_Q; q++) op[q] = e[q];
}

// final linear head: out[b][c] = bf[c] + sum_k outs[b][k] * Wf[c][k]
__global__ __launch_bounds__(192) void final_kernel(
    const float* __restrict__ Wf,
    const float* __restrict__ bf,
    float* __restrict__ out)
{
    __shared__ float row[K_FINAL];
    const int b   = blockIdx.x;
    const int tid = threadIdx.x;
    if (tid < K_FINAL) row[tid] = g_outs[b * K_FINAL + tid];
    __syncthreads();
    if (tid < N_CLASSES) {
        float a = bf[tid];
        const float* w = Wf + tid * K_FINAL;
#pragma unroll 8
        for (int k = 0; k < K_FINAL; k++) a += row[k] * w[k];
        out[b * N_CLASSES + tid] = a;
    }
}

extern "C" void kernel_launch(void* const* d_in, const int* in_sizes, int n_in,
                              void* d_out, int out_size)
{
    const float* features = (const float*)d_in[0];
    const float* Wp       = (const float*)d_in[1];
    const float* bp       = (const float*)d_in[2];
    const float* qw       = (const float*)d_in[3];
    const float* Wf       = (const float*)d_in[4];
    const float* bf       = (const float*)d_in[5];
    float* out = (float*)d_out;

    dim3 grid(B_TOTAL / BT, N_MOD);
    sim_kernel<<<grid, BT>>>(features, Wp, bp, qw);
    final_kernel<<<B_TOTAL, 192>>>(Wf, bf, out);
}

// round 2
// speedup vs baseline: 2.0781x; 2.0781x over previous
#include <cuda_runtime.h>
#include <math.h>

#define N_Q   6
#define N_CL  32
#define N_MOD 32
#define PART  64
#define B_TOTAL   2048
#define N_CLASSES 150
#define K_FINAL   (N_MOD * N_Q)   // 192
#define FEAT_DIM  2048

#define BT 128  // threads per block in sim kernel

// scratch for per-circuit expectation values: outs[b][p*6+q]
__device__ __align__(16) float g_outs[B_TOTAL * K_FINAL];

__global__ __launch_bounds__(BT, 2) void sim_kernel(
    const float* __restrict__ features,
    const float* __restrict__ Wp,
    const float* __restrict__ bp,
    const float* __restrict__ qw)
{
    __shared__ float s_cs[N_CL][N_Q][2];   // per-layer gate cos/sin (half angle)
    __shared__ float s_Wp[N_Q][PART];
    __shared__ float s_bp[N_Q];

    const int p   = blockIdx.y;                  // module
    const int b   = blockIdx.x * BT + threadIdx.x;
    const int tid = threadIdx.x;

    // cooperative loads: Wp, bp, and this module's layer-gate cos/sin
    for (int i = tid; i < N_Q * PART; i += BT)
        s_Wp[i / PART][i % PART] = Wp[i];
    if (tid < N_Q) s_bp[tid] = bp[tid];
    for (int i = tid; i < N_CL * N_Q; i += BT) {
        float a = qw[p * (N_CL * N_Q) + i];
        float s, c;
        sincosf(0.5f * a, &s, &c);
        s_cs[i / N_Q][i % N_Q][0] = c;
        s_cs[i / N_Q][i % N_Q][1] = s;
    }
    __syncthreads();

    // ---- angle projection: angles[q] = <features[b, p*64 : p*64+64], Wp[q]> + bp[q]
    float acc[N_Q];
#pragma unroll
    for (int q = 0; q < N_Q; q++) acc[q] = s_bp[q];
    const float4* fptr = (const float4*)(features + (size_t)b * FEAT_DIM + p * PART);
#pragma unroll
    for (int d4 = 0; d4 < PART / 4; d4++) {
        float4 f = fptr[d4];
#pragma unroll
        for (int q = 0; q < N_Q; q++) {
            acc[q] += f.x * s_Wp[q][d4 * 4 + 0];
            acc[q] += f.y * s_Wp[q][d4 * 4 + 1];
            acc[q] += f.z * s_Wp[q][d4 * 4 + 2];
            acc[q] += f.w * s_Wp[q][d4 * 4 + 3];
        }
    }
    float ca[N_Q], sa[N_Q];
#pragma unroll
    for (int q = 0; q < N_Q; q++) sincosf(0.5f * acc[q], &sa[q], &ca[q]);

    // ---- initial product state (real): sr[i] = prod_q (bit(i,5-q) ? sa[q] : ca[q])
    float sr[64], si[64];
    sr[0] = 1.0f;
#pragma unroll
    for (int q = 0; q < N_Q; q++) {
        const int len = 1 << q;
#pragma unroll
        for (int i = len - 1; i >= 0; i--) {
            float v = sr[i];
            sr[2 * i]     = v * ca[q];
            sr[2 * i + 1] = v * sa[q];
        }
    }
#pragma unroll
    for (int i = 0; i < 64; i++) si[i] = 0.0f;

    // ---- 32 layers: 6x RX then CNOT ring
    for (int l = 0; l < N_CL; l++) {
#pragma unroll
        for (int q = 0; q < N_Q; q++) {
            const float c = s_cs[l][q][0];
            const float s = s_cs[l][q][1];
            const int bit = 5 - q;       // wire q lives on index bit (5-q)
            const int m   = 1 << bit;
#pragma unroll
            for (int pr = 0; pr < 32; pr++) {
                const int i0 = ((pr >> bit) << (bit + 1)) | (pr & (m - 1));
                const int i1 = i0 | m;
                float r0 = sr[i0], u0 = si[i0];
                float r1 = sr[i1], u1 = si[i1];
                // RX(theta): [[c, -i s], [-i s, c]]
                sr[i0] = c * r0 + s * u1;
                si[i0] = c * u0 - s * r1;
                sr[i1] = c * r1 + s * u0;
                si[i1] = c * u1 - s * r0;
            }
        }
        // CNOT ring: ctrl q -> tgt (q+1)%6, applied in order q = 0..5
#pragma unroll
        for (int q = 0; q < N_Q; q++) {
            const int cb = 5 - q;
            const int tb = 5 - ((q + 1) % N_Q);
            const int tm = 1 << tb;
#pragma unroll
            for (int i = 0; i < 64; i++) {
                if ((((i >> cb) & 1) == 1) && (((i >> tb) & 1) == 0)) {
                    const int j = i | tm;
                    float t;
                    t = sr[i]; sr[i] = sr[j]; sr[j] = t;
                    t = si[i]; si[i] = si[j]; si[j] = t;
                }
            }
        }
    }

    // ---- Z expectations: e[q] = sum_i probs[i] * (1 - 2*bit(i,5-q))
    float e[N_Q];
#pragma unroll
    for (int q = 0; q < N_Q; q++) e[q] = 0.0f;
#pragma unroll
    for (int i = 0; i < 64; i++) {
        float pi = sr[i] * sr[i] + si[i] * si[i];
#pragma unroll
        for (int q = 0; q < N_Q; q++) {
            if ((i >> (5 - q)) & 1) e[q] -= pi; else e[q] += pi;
        }
    }

    float* op = g_outs + (size_t)b * K_FINAL + p * N_Q;
#pragma unroll
    for (int q = 0; q < N_Q; q++) op[q] = e[q];
}

// ---------------------------------------------------------------------------
// final linear head as a register-tiled GEMM:
//   out[2048][150] = g_outs[2048][192] @ Wf[150][192]^T + bf
// Block: 32 batch rows, all 150 classes. 240 active threads,
// each computes a 4(row) x 5(class) register tile. A-tile staged in smem.
// ---------------------------------------------------------------------------
#define FB_M 32                 // batch rows per block
#define FB_K4 (K_FINAL / 4)     // 48 float4 per row

__global__ __launch_bounds__(256) void final_kernel(
    const float* __restrict__ Wf,
    const float* __restrict__ bf,
    float* __restrict__ out)
{
    __shared__ float4 sA[FB_M][FB_K4];   // 32 x 192 floats = 24 KB

    const int tid = threadIdx.x;
    const int b0  = blockIdx.x * FB_M;

    // coalesced load of the A tile (rows are contiguous in g_outs)
    const float4* src = (const float4*)(g_outs + (size_t)b0 * K_FINAL);
    float4* dst = (float4*)sA;
#pragma unroll
    for (int i = 0; i < (FB_M * FB_K4) / 256; i++)
        dst[tid + i * 256] = src[tid + i * 256];
    __syncthreads();

    if (tid >= 240) return;
    const int rowg = tid / 30;        // 0..7  -> rows rowg*4 .. +3
    const int colg = tid % 30;        // 0..29 -> classes colg*5 .. +4

    float acc[4][5];
#pragma unroll
    for (int m = 0; m < 4; m++)
#pragma unroll
        for (int n = 0; n < 5; n++) acc[m][n] = 0.0f;

    const float4* w0 = (const float4*)(Wf + (size_t)(colg * 5) * K_FINAL);

#pragma unroll 2
    for (int k4 = 0; k4 < FB_K4; k4++) {
        float4 wv[5];
#pragma unroll
        for (int n = 0; n < 5; n++)
            wv[n] = __ldg(w0 + (size_t)n * FB_K4 + k4);
        float4 av[4];
#pragma unroll
        for (int m = 0; m < 4; m++)
            av[m] = sA[rowg * 4 + m][k4];
#pragma unroll
        for (int m = 0; m < 4; m++) {
#pragma unroll
            for (int n = 0; n < 5; n++) {
                acc[m][n] += av[m].x * wv[n].x;
                acc[m][n] += av[m].y * wv[n].y;
                acc[m][n] += av[m].z * wv[n].z;
                acc[m][n] += av[m].w * wv[n].w;
            }
        }
    }

#pragma unroll
    for (int n = 0; n < 5; n++) {
        const int c = colg * 5 + n;
        const float bias = bf[c];
#pragma unroll
        for (int m = 0; m < 4; m++) {
            const int b = b0 + rowg * 4 + m;
            out[(size_t)b * N_CLASSES + c] = acc[m][n] + bias;
        }
    }
}

extern "C" void kernel_launch(void* const* d_in, const int* in_sizes, int n_in,
                              void* d_out, int out_size)
{
    const float* features = (const float*)d_in[0];
    const float* Wp       = (const float*)d_in[1];
    const float* bp       = (const float*)d_in[2];
    const float* qw       = (const float*)d_in[3];
    const float* Wf       = (const float*)d_in[4];
    const float* bf       = (const float*)d_in[5];
    float* out = (float*)d_out;

    dim3 grid(B_TOTAL / BT, N_MOD);
    sim_kernel<<<grid, BT>>>(features, Wp, bp, qw);
    final_kernel<<<B_TOTAL / FB_M, 256>>>(Wf, bf, out);
}